// round 15
// baseline (speedup 1.0000x reference)
#include <cuda_runtime.h>

// Fused loss: CE + Dice + Focal + 0.5 * Lovasz — SINGLE KERNEL.
// logits: [4, 19, 512, 1024] f32; masks: [4, 512, 1024] int32; out: scalar f32.
// R15: R12 base (static partition) + NBUCK=1024 (width 1/128: halves smem
// zero/dump/merge; scan becomes single-chunk, merge = 1 word/thread) + direct
// target-logit load (kills the 19-deep c==t select chain).

#define NC 19
#define HW (512 * 1024)            // 1<<19
#define NPIX (4 * HW)
#define NBUCK 1024
#define HWORDS (NC * NBUCK)        // 19456
#define NBLK 148
#define NTHR 1024
#define STRIDE (NBLK * NTHR)
#define SMEM_BYTES (HWORDS * 4)    // 77824
#define LOGITS_ELEMS (4 * NC * HW)

__device__ unsigned g_part[NBLK * (size_t)HWORDS]; // per-block hist partials
__device__ float    g_bsp[NBLK][NC];               // per-block sum_prob
__device__ float    g_bin[NBLK][NC];               // per-block intersection
__device__ unsigned g_bct[NBLK][NC];               // per-block class counts
__device__ float    g_bce[NBLK];                   // per-block ce sum
__device__ float    g_bfo[NBLK];                   // per-block focal sum
__device__ float    g_lov[NC];                     // per-class lovasz
__device__ float    g_dice[NC];                    // per-class dice term
__device__ unsigned g_pres[NC];                    // per-class present flag
__device__ float    g_cefo[2];                     // total ce, focal
__device__ unsigned g_c1 = 0;                      // dump-complete barrier
__device__ unsigned g_c3 = 0;                      // completion counter

// Predicated shared reduction; predicate = (bk < 1024) as unsigned rejects
// er<=0 (negative floor -> huge unsigned) and er>=8 in one compare.
__device__ __forceinline__ void hist_insert(unsigned addr, unsigned bk,
                                            unsigned val) {
    asm volatile(
        "{\n\t"
        ".reg .pred p;\n\t"
        "setp.lt.u32 p, %1, 1024;\n\t"
        "@p red.shared.add.u32 [%0], %2;\n\t"
        "}"
        :: "r"(addr), "r"(bk), "r"(val));
}

// ---------------------------------------------------------------------------
__global__ void __launch_bounds__(NTHR, 1) fused_kernel(
    const float* __restrict__ logits, const int* __restrict__ masks,
    float* __restrict__ out)
{
    extern __shared__ unsigned sh[];      // phase A: [HWORDS] hist; B: reused
    __shared__ float s_sp[NC], s_in[NC];
    __shared__ unsigned s_ct[NC];
    __shared__ float s_ce, s_fo;
    __shared__ unsigned wF[32], wB[32];
    __shared__ unsigned sPv;
    __shared__ double red[32];
    __shared__ int s_last;

    const int tid = threadIdx.x;
    const int bid = blockIdx.x;
    const int w = tid >> 5, l = tid & 31;

    // ============================ PHASE A: main ============================
    {
        uint4* sh4 = reinterpret_cast<uint4*>(sh);
        const uint4 z = make_uint4(0u, 0u, 0u, 0u);
        for (int i = tid; i < HWORDS / 4; i += NTHR) sh4[i] = z;
    }
    if (tid < NC) { s_sp[tid] = 0.f; s_in[tid] = 0.f; s_ct[tid] = 0u; }
    if (tid == 0) { s_ce = 0.f; s_fo = 0.f; }
    __syncthreads();

    const unsigned sh_base = (unsigned)__cvta_generic_to_shared(sh);

    float sp[NC];
#pragma unroll
    for (int c = 0; c < NC; c++) sp[c] = 0.f;
    float ce = 0.f, fo = 0.f;

    for (unsigned pix = bid * NTHR + tid; pix < NPIX; pix += STRIDE) {
        const unsigned b  = pix >> 19;
        const unsigned hw = pix & (HW - 1);
        const float* base = logits + ((size_t)(b * NC) << 19) + hw;

        const int t = min(max(__ldcs(masks + pix), 0), NC - 1);
        // direct target-logit load (L1 hit; replaces 19-deep select chain)
        const float lt = __ldcs(base + ((size_t)t << 19));

        float e[NC];
        float s = 0.f;
#pragma unroll
        for (int c = 0; c < NC; c++) {
            const float v = __ldcs(base + ((size_t)c << 19));
            const float ex = __expf(v);
            e[c] = ex;
            s += ex;
            const int bk = __float2int_rd(fmaf(v, 128.f, 128.f));
            hist_insert(sh_base + ((unsigned)(c * NBUCK + bk) << 2),
                        (unsigned)bk, 1u);
        }
        {   // target fixup: cancel wrong bg insert, add true fg insert
            const int bw = __float2int_rd(fmaf(lt, 128.f, 128.f));
            hist_insert(sh_base + ((unsigned)(t * NBUCK + bw) << 2),
                        (unsigned)bw, 0xFFFFFFFFu);
            const int bf = __float2int_rd(fmaf(lt, -128.f, 128.f));
            hist_insert(sh_base + ((unsigned)(t * NBUCK + bf) << 2),
                        (unsigned)bf, 65536u);
        }

        const float logpt = lt - __logf(s);
        const float pt = __expf(logpt);
        ce -= logpt;
        fo -= 0.25f * (1.f - pt) * (1.f - pt) * logpt;
        atomicAdd(&s_in[t], pt);
        atomicAdd(&s_ct[t], 1u);

        const float inv = __fdividef(1.f, s);
#pragma unroll
        for (int c = 0; c < NC; c++) sp[c] += e[c] * inv;
    }

#pragma unroll
    for (int c = 0; c < NC; c++) {
        float v = sp[c];
#pragma unroll
        for (int d = 16; d; d >>= 1) v += __shfl_down_sync(0xffffffffu, v, d);
        if (l == 0) atomicAdd(&s_sp[c], v);
    }
#pragma unroll
    for (int d = 16; d; d >>= 1) {
        ce += __shfl_down_sync(0xffffffffu, ce, d);
        fo += __shfl_down_sync(0xffffffffu, fo, d);
    }
    if (l == 0) { atomicAdd(&s_ce, ce); atomicAdd(&s_fo, fo); }
    __syncthreads();

    if (tid < NC) {
        g_bsp[bid][tid] = s_sp[tid];
        g_bin[bid][tid] = s_in[tid];
        g_bct[bid][tid] = s_ct[tid];
    }
    if (tid == 32) g_bce[bid] = s_ce;
    if (tid == 33) g_bfo[bid] = s_fo;

    {
        uint4* dst4 = reinterpret_cast<uint4*>(g_part + (size_t)bid * HWORDS);
        const uint4* sh4 = reinterpret_cast<const uint4*>(sh);
        for (int i = tid; i < HWORDS / 4; i += NTHR) dst4[i] = sh4[i];
    }
    __syncthreads();   // all reads of sh done before phase B reuses it

    // ===================== BARRIER: dumps visible chip-wide =================
    if (tid == 0) {
        __threadfence();
        atomicAdd(&g_c1, 1u);
    }

    // ============================ PHASE B ==================================
    const int c = bid;
    if (c <= NC) {
        if (tid == 0) {
            while (atomicAdd(&g_c1, 0u) < (unsigned)NBLK) __nanosleep(64);
        }
        __syncthreads();
        __threadfence();   // acquire: partials + per-block scalars visible

        if (c == NC) {
            // scalar block: warp 0 = ce, warp 1 = fo, warps 2..20 = dice
            if (w == 0) {
                float v = 0.f;
                for (int r = l; r < NBLK; r += 32) v += g_bce[r];
#pragma unroll
                for (int d = 16; d; d >>= 1) v += __shfl_down_sync(0xffffffffu, v, d);
                if (l == 0) g_cefo[0] = v;
            } else if (w == 1) {
                float v = 0.f;
                for (int r = l; r < NBLK; r += 32) v += g_bfo[r];
#pragma unroll
                for (int d = 16; d; d >>= 1) v += __shfl_down_sync(0xffffffffu, v, d);
                if (l == 0) g_cefo[1] = v;
            } else if (w - 2 < NC) {
                const int cc = w - 2;
                float spv = 0.f, inv = 0.f;
                unsigned ct = 0u;
                for (int r = l; r < NBLK; r += 32) {
                    spv += g_bsp[r][cc];
                    inv += g_bin[r][cc];
                    ct  += g_bct[r][cc];
                }
#pragma unroll
                for (int d = 16; d; d >>= 1) {
                    spv += __shfl_down_sync(0xffffffffu, spv, d);
                    inv += __shfl_down_sync(0xffffffffu, inv, d);
                    ct  += __shfl_down_sync(0xffffffffu, ct, d);
                }
                if (l == 0) {
                    g_pres[cc] = ct;
                    const float u = spv + (float)ct;
                    g_dice[cc] = (ct > 0u)
                        ? __fdividef(2.f * inv + 1e-8f, u + 1e-8f) : 0.f;
                }
            }
        } else {
            // ---- merge class c's 148 partials: thread tid owns bucket tid --
            {
                unsigned acc = 0u;
                const unsigned off = (unsigned)c * NBUCK + tid;
#pragma unroll 4
                for (int r = 0; r < NBLK; r++)
                    acc += g_part[(size_t)r * HWORDS + off];
                sh[tid] = acc;
            }
            if (tid < 32) {   // per-class total count P
                unsigned p = 0u;
                for (int r = tid; r < NBLK; r += 32) p += g_bct[r][c];
#pragma unroll
                for (int d = 16; d; d >>= 1) p += __shfl_down_sync(0xffffffffu, p, d);
                if (tid == 0) sPv = p;
            }
            __syncthreads();

            const unsigned P = sPv;
            if (tid == 0) g_lov[c] = 0.f;
            double acc = 0.0;
            if (P > 0u) {
                const float Pf = (float)P;
                // single-chunk descending scan: 1024 buckets, 1024 threads
                const int idx = (NBUCK - 1) - tid;
                const unsigned cnt = sh[idx];
                const unsigned f = cnt >> 16;
                const unsigned gq = cnt & 0xFFFFu;

                unsigned fi = f, gi = gq;
#pragma unroll
                for (int d = 1; d < 32; d <<= 1) {
                    unsigned a = __shfl_up_sync(0xffffffffu, fi, d);
                    unsigned bb = __shfl_up_sync(0xffffffffu, gi, d);
                    if (l >= d) { fi += a; gi += bb; }
                }
                if (l == 31) { wF[w] = fi; wB[w] = gi; }
                __syncthreads();

                unsigned aF = 0u, aB = 0u;
                for (int k = 0; k < w; k++) { aF += wF[k]; aB += wB[k]; }

                if (cnt) {
                    const float Fi = (float)(aF + fi);
                    const float Bi = (float)(aB + gi);
                    const float Fe = Fi - (float)f;
                    const float Be = Bi - (float)gq;
                    const float e_rep = ((float)idx + 0.5f) * (1.0f / 128.0f);
                    const float num = (Pf - Fe) * (float)gq + (float)f * (Pf + Be);
                    const float den = (Pf + Be) * (Pf + Bi);
                    acc = (double)(e_rep * __fdividef(num, den));
                }
                __syncthreads();

#pragma unroll
                for (int d = 16; d; d >>= 1) acc += __shfl_down_sync(0xffffffffu, acc, d);
                if (l == 0) red[w] = acc;
                __syncthreads();
                if (tid < 32) {
                    double v = red[tid];
#pragma unroll
                    for (int d = 16; d; d >>= 1) v += __shfl_down_sync(0xffffffffu, v, d);
                    if (tid == 0) g_lov[c] = (float)v;
                }
            }
        }
    }

    // ==================== COMPLETION: last block combines ==================
    __threadfence();
    __syncthreads();
    if (tid == 0) s_last = (atomicAdd(&g_c3, 1u) == (unsigned)(NBLK - 1));
    __syncthreads();
    if (s_last) {
        __threadfence();   // acquire all scan/scalar results
        if (tid < 32) {
            float lov = 0.f, ds = 0.f, np = 0.f;
            if (tid < NC) {
                lov = g_lov[tid];
                if (g_pres[tid] > 0u) { ds = g_dice[tid]; np = 1.f; }
            }
#pragma unroll
            for (int d = 16; d; d >>= 1) {
                lov += __shfl_down_sync(0xffffffffu, lov, d);
                ds  += __shfl_down_sync(0xffffffffu, ds, d);
                np  += __shfl_down_sync(0xffffffffu, np, d);
            }
            if (tid == 0) {
                const double Nd = (double)NPIX;
                const double dice = (np > 0.f) ? (1.0 - (double)ds / (double)np) : 1.0;
                out[0] = (float)((double)g_cefo[0] / Nd + dice +
                                 (double)g_cefo[1] / Nd +
                                 0.5 * (double)lov / (double)NC);
                g_c1 = 0u;     // reset for next replay; safe: all 148 arrived
                g_c3 = 0u;
                __threadfence();
            }
        }
    }
}

// ---------------------------------------------------------------------------
extern "C" void kernel_launch(void* const* d_in, const int* in_sizes, int n_in,
                              void* d_out, int out_size)
{
    const float* logits;
    const int* masks;
    if (in_sizes[0] == LOGITS_ELEMS) {
        logits = (const float*)d_in[0];
        masks  = (const int*)d_in[1];
    } else {
        logits = (const float*)d_in[1];
        masks  = (const int*)d_in[0];
    }
    float* out = (float*)d_out;

    cudaFuncSetAttribute(fused_kernel,
                         cudaFuncAttributeMaxDynamicSharedMemorySize, SMEM_BYTES);

    fused_kernel<<<NBLK, NTHR, SMEM_BYTES>>>(logits, masks, out);
}

// round 16
// speedup vs baseline: 1.0543x; 1.0543x over previous
#include <cuda_runtime.h>

// Fused loss: CE + Dice + Focal + 0.5 * Lovasz — SINGLE KERNEL.
// logits: [4, 19, 512, 1024] f32; masks: [4, 512, 1024] int32; out: scalar f32.
// R16: R15 epilogue (NBUCK=1024, single-chunk scan, 1-word merge) + phase A
// dependency fix: lt via select chain (overlaps class loads; R15's dependent
// lt-load serialized mask->lt ~1000cyc/iter) + mask prefetched one iteration
// ahead (removes the mask LDG from the per-iteration critical path).

#define NC 19
#define HW (512 * 1024)            // 1<<19
#define NPIX (4 * HW)
#define NBUCK 1024
#define HWORDS (NC * NBUCK)        // 19456
#define NBLK 148
#define NTHR 1024
#define STRIDE (NBLK * NTHR)
#define SMEM_BYTES (HWORDS * 4)    // 77824
#define LOGITS_ELEMS (4 * NC * HW)

__device__ unsigned g_part[NBLK * (size_t)HWORDS]; // per-block hist partials
__device__ float    g_bsp[NBLK][NC];               // per-block sum_prob
__device__ float    g_bin[NBLK][NC];               // per-block intersection
__device__ unsigned g_bct[NBLK][NC];               // per-block class counts
__device__ float    g_bce[NBLK];                   // per-block ce sum
__device__ float    g_bfo[NBLK];                   // per-block focal sum
__device__ float    g_lov[NC];                     // per-class lovasz
__device__ float    g_dice[NC];                    // per-class dice term
__device__ unsigned g_pres[NC];                    // per-class present flag
__device__ float    g_cefo[2];                     // total ce, focal
__device__ unsigned g_c1 = 0;                      // dump-complete barrier
__device__ unsigned g_c3 = 0;                      // completion counter

// Predicated shared reduction; predicate = (bk < 1024) as unsigned rejects
// er<=0 (negative floor -> huge unsigned) and er>=8 in one compare.
__device__ __forceinline__ void hist_insert(unsigned addr, unsigned bk,
                                            unsigned val) {
    asm volatile(
        "{\n\t"
        ".reg .pred p;\n\t"
        "setp.lt.u32 p, %1, 1024;\n\t"
        "@p red.shared.add.u32 [%0], %2;\n\t"
        "}"
        :: "r"(addr), "r"(bk), "r"(val));
}

// ---------------------------------------------------------------------------
__global__ void __launch_bounds__(NTHR, 1) fused_kernel(
    const float* __restrict__ logits, const int* __restrict__ masks,
    float* __restrict__ out)
{
    extern __shared__ unsigned sh[];      // phase A: [HWORDS] hist; B: reused
    __shared__ float s_sp[NC], s_in[NC];
    __shared__ unsigned s_ct[NC];
    __shared__ float s_ce, s_fo;
    __shared__ unsigned wF[32], wB[32];
    __shared__ unsigned sPv;
    __shared__ double red[32];
    __shared__ int s_last;

    const int tid = threadIdx.x;
    const int bid = blockIdx.x;
    const int w = tid >> 5, l = tid & 31;

    // ============================ PHASE A: main ============================
    {
        uint4* sh4 = reinterpret_cast<uint4*>(sh);
        const uint4 z = make_uint4(0u, 0u, 0u, 0u);
        for (int i = tid; i < HWORDS / 4; i += NTHR) sh4[i] = z;
    }
    if (tid < NC) { s_sp[tid] = 0.f; s_in[tid] = 0.f; s_ct[tid] = 0u; }
    if (tid == 0) { s_ce = 0.f; s_fo = 0.f; }
    __syncthreads();

    const unsigned sh_base = (unsigned)__cvta_generic_to_shared(sh);

    float sp[NC];
#pragma unroll
    for (int c = 0; c < NC; c++) sp[c] = 0.f;
    float ce = 0.f, fo = 0.f;

    const unsigned pix0 = bid * NTHR + tid;
    int t_raw = (pix0 < NPIX) ? __ldcs(masks + pix0) : 0;

    for (unsigned pix = pix0; pix < NPIX; pix += STRIDE) {
        const int t = min(max(t_raw, 0), NC - 1);
        // prefetch next iteration's mask: removes the mask LDG from the
        // critical path of the NEXT iteration's dependence tree
        const unsigned nxt = pix + STRIDE;
        if (nxt < NPIX) t_raw = __ldcs(masks + nxt);

        const unsigned b  = pix >> 19;
        const unsigned hw = pix & (HW - 1);
        const float* base = logits + ((size_t)(b * NC) << 19) + hw;

        float e[NC];
        float s = 0.f, lt = 0.f;
#pragma unroll
        for (int c = 0; c < NC; c++) {
            const float v = __ldcs(base + ((size_t)c << 19));
            const float ex = __expf(v);
            e[c] = ex;
            s += ex;
            if (c == t) lt = v;   // select chain: overlaps the class loads
            const int bk = __float2int_rd(fmaf(v, 128.f, 128.f));
            hist_insert(sh_base + ((unsigned)(c * NBUCK + bk) << 2),
                        (unsigned)bk, 1u);
        }
        {   // target fixup: cancel wrong bg insert, add true fg insert
            const int bw = __float2int_rd(fmaf(lt, 128.f, 128.f));
            hist_insert(sh_base + ((unsigned)(t * NBUCK + bw) << 2),
                        (unsigned)bw, 0xFFFFFFFFu);
            const int bf = __float2int_rd(fmaf(lt, -128.f, 128.f));
            hist_insert(sh_base + ((unsigned)(t * NBUCK + bf) << 2),
                        (unsigned)bf, 65536u);
        }

        const float logpt = lt - __logf(s);
        const float pt = __expf(logpt);
        ce -= logpt;
        fo -= 0.25f * (1.f - pt) * (1.f - pt) * logpt;
        atomicAdd(&s_in[t], pt);
        atomicAdd(&s_ct[t], 1u);

        const float inv = __fdividef(1.f, s);
#pragma unroll
        for (int c = 0; c < NC; c++) sp[c] += e[c] * inv;
    }

#pragma unroll
    for (int c = 0; c < NC; c++) {
        float v = sp[c];
#pragma unroll
        for (int d = 16; d; d >>= 1) v += __shfl_down_sync(0xffffffffu, v, d);
        if (l == 0) atomicAdd(&s_sp[c], v);
    }
#pragma unroll
    for (int d = 16; d; d >>= 1) {
        ce += __shfl_down_sync(0xffffffffu, ce, d);
        fo += __shfl_down_sync(0xffffffffu, fo, d);
    }
    if (l == 0) { atomicAdd(&s_ce, ce); atomicAdd(&s_fo, fo); }
    __syncthreads();

    if (tid < NC) {
        g_bsp[bid][tid] = s_sp[tid];
        g_bin[bid][tid] = s_in[tid];
        g_bct[bid][tid] = s_ct[tid];
    }
    if (tid == 32) g_bce[bid] = s_ce;
    if (tid == 33) g_bfo[bid] = s_fo;

    {
        uint4* dst4 = reinterpret_cast<uint4*>(g_part + (size_t)bid * HWORDS);
        const uint4* sh4 = reinterpret_cast<const uint4*>(sh);
        for (int i = tid; i < HWORDS / 4; i += NTHR) dst4[i] = sh4[i];
    }
    __syncthreads();   // all reads of sh done before phase B reuses it

    // ===================== BARRIER: dumps visible chip-wide =================
    if (tid == 0) {
        __threadfence();
        atomicAdd(&g_c1, 1u);
    }

    // ============================ PHASE B ==================================
    const int c = bid;
    if (c <= NC) {
        if (tid == 0) {
            while (atomicAdd(&g_c1, 0u) < (unsigned)NBLK) __nanosleep(64);
        }
        __syncthreads();
        __threadfence();   // acquire: partials + per-block scalars visible

        if (c == NC) {
            // scalar block: warp 0 = ce, warp 1 = fo, warps 2..20 = dice
            if (w == 0) {
                float v = 0.f;
                for (int r = l; r < NBLK; r += 32) v += g_bce[r];
#pragma unroll
                for (int d = 16; d; d >>= 1) v += __shfl_down_sync(0xffffffffu, v, d);
                if (l == 0) g_cefo[0] = v;
            } else if (w == 1) {
                float v = 0.f;
                for (int r = l; r < NBLK; r += 32) v += g_bfo[r];
#pragma unroll
                for (int d = 16; d; d >>= 1) v += __shfl_down_sync(0xffffffffu, v, d);
                if (l == 0) g_cefo[1] = v;
            } else if (w - 2 < NC) {
                const int cc = w - 2;
                float spv = 0.f, inv = 0.f;
                unsigned ct = 0u;
                for (int r = l; r < NBLK; r += 32) {
                    spv += g_bsp[r][cc];
                    inv += g_bin[r][cc];
                    ct  += g_bct[r][cc];
                }
#pragma unroll
                for (int d = 16; d; d >>= 1) {
                    spv += __shfl_down_sync(0xffffffffu, spv, d);
                    inv += __shfl_down_sync(0xffffffffu, inv, d);
                    ct  += __shfl_down_sync(0xffffffffu, ct, d);
                }
                if (l == 0) {
                    g_pres[cc] = ct;
                    const float u = spv + (float)ct;
                    g_dice[cc] = (ct > 0u)
                        ? __fdividef(2.f * inv + 1e-8f, u + 1e-8f) : 0.f;
                }
            }
        } else {
            // ---- merge class c's 148 partials: thread tid owns bucket tid --
            {
                unsigned acc = 0u;
                const unsigned off = (unsigned)c * NBUCK + tid;
#pragma unroll 4
                for (int r = 0; r < NBLK; r++)
                    acc += g_part[(size_t)r * HWORDS + off];
                sh[tid] = acc;
            }
            if (tid < 32) {   // per-class total count P
                unsigned p = 0u;
                for (int r = tid; r < NBLK; r += 32) p += g_bct[r][c];
#pragma unroll
                for (int d = 16; d; d >>= 1) p += __shfl_down_sync(0xffffffffu, p, d);
                if (tid == 0) sPv = p;
            }
            __syncthreads();

            const unsigned P = sPv;
            if (tid == 0) g_lov[c] = 0.f;
            double acc = 0.0;
            if (P > 0u) {
                const float Pf = (float)P;
                // single-chunk descending scan: 1024 buckets, 1024 threads
                const int idx = (NBUCK - 1) - tid;
                const unsigned cnt = sh[idx];
                const unsigned f = cnt >> 16;
                const unsigned gq = cnt & 0xFFFFu;

                unsigned fi = f, gi = gq;
#pragma unroll
                for (int d = 1; d < 32; d <<= 1) {
                    unsigned a = __shfl_up_sync(0xffffffffu, fi, d);
                    unsigned bb = __shfl_up_sync(0xffffffffu, gi, d);
                    if (l >= d) { fi += a; gi += bb; }
                }
                if (l == 31) { wF[w] = fi; wB[w] = gi; }
                __syncthreads();

                unsigned aF = 0u, aB = 0u;
                for (int k = 0; k < w; k++) { aF += wF[k]; aB += wB[k]; }

                if (cnt) {
                    const float Fi = (float)(aF + fi);
                    const float Bi = (float)(aB + gi);
                    const float Fe = Fi - (float)f;
                    const float Be = Bi - (float)gq;
                    const float e_rep = ((float)idx + 0.5f) * (1.0f / 128.0f);
                    const float num = (Pf - Fe) * (float)gq + (float)f * (Pf + Be);
                    const float den = (Pf + Be) * (Pf + Bi);
                    acc = (double)(e_rep * __fdividef(num, den));
                }
                __syncthreads();

#pragma unroll
                for (int d = 16; d; d >>= 1) acc += __shfl_down_sync(0xffffffffu, acc, d);
                if (l == 0) red[w] = acc;
                __syncthreads();
                if (tid < 32) {
                    double v = red[tid];
#pragma unroll
                    for (int d = 16; d; d >>= 1) v += __shfl_down_sync(0xffffffffu, v, d);
                    if (tid == 0) g_lov[c] = (float)v;
                }
            }
        }
    }

    // ==================== COMPLETION: last block combines ==================
    __threadfence();
    __syncthreads();
    if (tid == 0) s_last = (atomicAdd(&g_c3, 1u) == (unsigned)(NBLK - 1));
    __syncthreads();
    if (s_last) {
        __threadfence();   // acquire all scan/scalar results
        if (tid < 32) {
            float lov = 0.f, ds = 0.f, np = 0.f;
            if (tid < NC) {
                lov = g_lov[tid];
                if (g_pres[tid] > 0u) { ds = g_dice[tid]; np = 1.f; }
            }
#pragma unroll
            for (int d = 16; d; d >>= 1) {
                lov += __shfl_down_sync(0xffffffffu, lov, d);
                ds  += __shfl_down_sync(0xffffffffu, ds, d);
                np  += __shfl_down_sync(0xffffffffu, np, d);
            }
            if (tid == 0) {
                const double Nd = (double)NPIX;
                const double dice = (np > 0.f) ? (1.0 - (double)ds / (double)np) : 1.0;
                out[0] = (float)((double)g_cefo[0] / Nd + dice +
                                 (double)g_cefo[1] / Nd +
                                 0.5 * (double)lov / (double)NC);
                g_c1 = 0u;     // reset for next replay; safe: all 148 arrived
                g_c3 = 0u;
                __threadfence();
            }
        }
    }
}

// ---------------------------------------------------------------------------
extern "C" void kernel_launch(void* const* d_in, const int* in_sizes, int n_in,
                              void* d_out, int out_size)
{
    const float* logits;
    const int* masks;
    if (in_sizes[0] == LOGITS_ELEMS) {
        logits = (const float*)d_in[0];
        masks  = (const int*)d_in[1];
    } else {
        logits = (const float*)d_in[1];
        masks  = (const int*)d_in[0];
    }
    float* out = (float*)d_out;

    cudaFuncSetAttribute(fused_kernel,
                         cudaFuncAttributeMaxDynamicSharedMemorySize, SMEM_BYTES);

    fused_kernel<<<NBLK, NTHR, SMEM_BYTES>>>(logits, masks, out);
}

// round 17
// speedup vs baseline: 1.0552x; 1.0009x over previous
#include <cuda_runtime.h>

// Fused loss: CE + Dice + Focal + 0.5 * Lovasz — SINGLE KERNEL.
// logits: [4, 19, 512, 1024] f32; masks: [4, 512, 1024] int32; out: scalar f32.
// R17: R16 + per-iteration critical-path cuts: pt = e[t]*inv (kills one
// dependent MUFU exp), target-skip folded into the bg-insert predicate
// (drops the cancel RED, 21->20 smem REDs/pixel), 4-way interleaved
// softmax-denominator accumulation (76cyc chain -> ~28cyc).

#define NC 19
#define HW (512 * 1024)            // 1<<19
#define NPIX (4 * HW)
#define NBUCK 1024
#define HWORDS (NC * NBUCK)        // 19456
#define NBLK 148
#define NTHR 1024
#define STRIDE (NBLK * NTHR)
#define SMEM_BYTES (HWORDS * 4)    // 77824
#define LOGITS_ELEMS (4 * NC * HW)

__device__ unsigned g_part[NBLK * (size_t)HWORDS]; // per-block hist partials
__device__ float    g_bsp[NBLK][NC];               // per-block sum_prob
__device__ float    g_bin[NBLK][NC];               // per-block intersection
__device__ unsigned g_bct[NBLK][NC];               // per-block class counts
__device__ float    g_bce[NBLK];                   // per-block ce sum
__device__ float    g_bfo[NBLK];                   // per-block focal sum
__device__ float    g_lov[NC];                     // per-class lovasz
__device__ float    g_dice[NC];                    // per-class dice term
__device__ unsigned g_pres[NC];                    // per-class present flag
__device__ float    g_cefo[2];                     // total ce, focal
__device__ unsigned g_c1 = 0;                      // dump-complete barrier
__device__ unsigned g_c3 = 0;                      // completion counter

// Predicated shared reduction; predicate = (bk < 1024) as unsigned rejects
// er<=0 (negative floor -> huge unsigned), er>=8, AND the target class
// (caller passes bk=0xFFFFFFFF to disable).
__device__ __forceinline__ void hist_insert(unsigned addr, unsigned bk,
                                            unsigned val) {
    asm volatile(
        "{\n\t"
        ".reg .pred p;\n\t"
        "setp.lt.u32 p, %1, 1024;\n\t"
        "@p red.shared.add.u32 [%0], %2;\n\t"
        "}"
        :: "r"(addr), "r"(bk), "r"(val));
}

// ---------------------------------------------------------------------------
__global__ void __launch_bounds__(NTHR, 1) fused_kernel(
    const float* __restrict__ logits, const int* __restrict__ masks,
    float* __restrict__ out)
{
    extern __shared__ unsigned sh[];      // phase A: [HWORDS] hist; B: reused
    __shared__ float s_sp[NC], s_in[NC];
    __shared__ unsigned s_ct[NC];
    __shared__ float s_ce, s_fo;
    __shared__ unsigned wF[32], wB[32];
    __shared__ unsigned sPv;
    __shared__ double red[32];
    __shared__ int s_last;

    const int tid = threadIdx.x;
    const int bid = blockIdx.x;
    const int w = tid >> 5, l = tid & 31;

    // ============================ PHASE A: main ============================
    {
        uint4* sh4 = reinterpret_cast<uint4*>(sh);
        const uint4 z = make_uint4(0u, 0u, 0u, 0u);
        for (int i = tid; i < HWORDS / 4; i += NTHR) sh4[i] = z;
    }
    if (tid < NC) { s_sp[tid] = 0.f; s_in[tid] = 0.f; s_ct[tid] = 0u; }
    if (tid == 0) { s_ce = 0.f; s_fo = 0.f; }
    __syncthreads();

    const unsigned sh_base = (unsigned)__cvta_generic_to_shared(sh);

    float sp[NC];
#pragma unroll
    for (int c = 0; c < NC; c++) sp[c] = 0.f;
    float ce = 0.f, fo = 0.f;

    const unsigned pix0 = bid * NTHR + tid;
    int t_raw = (pix0 < NPIX) ? __ldcs(masks + pix0) : 0;

    for (unsigned pix = pix0; pix < NPIX; pix += STRIDE) {
        const int t = min(max(t_raw, 0), NC - 1);
        // prefetch next iteration's mask (off the critical path)
        const unsigned nxt = pix + STRIDE;
        if (nxt < NPIX) t_raw = __ldcs(masks + nxt);

        const unsigned b  = pix >> 19;
        const unsigned hw = pix & (HW - 1);
        const float* base = logits + ((size_t)(b * NC) << 19) + hw;

        float e[NC];
        float s4[4] = {0.f, 0.f, 0.f, 0.f};
        float lt = 0.f, et = 1.f;
#pragma unroll
        for (int c = 0; c < NC; c++) {
            const float v = __ldcs(base + ((size_t)c << 19));
            const float ex = __expf(v);
            e[c] = ex;
            s4[c & 3] += ex;                 // 4 parallel add chains
            const bool f = (c == t);
            if (f) { lt = v; et = ex; }      // select chain (overlaps loads)
            const int bk = __float2int_rd(fmaf(v, 128.f, 128.f));
            const unsigned bkx = f ? 0xFFFFFFFFu : (unsigned)bk;  // skip @ t
            hist_insert(sh_base + ((unsigned)(c * NBUCK + bk) << 2),
                        bkx, 1u);
        }
        const float s = (s4[0] + s4[1]) + (s4[2] + s4[3]);
        {   // fg insert for the target class
            const int bf = __float2int_rd(fmaf(lt, -128.f, 128.f));
            hist_insert(sh_base + ((unsigned)(t * NBUCK + bf) << 2),
                        (unsigned)bf, 65536u);
        }

        const float inv = __fdividef(1.f, s);
        const float logpt = lt - __logf(s);
        const float pt = et * inv;           // = exp(logpt), no extra MUFU
        ce -= logpt;
        fo -= 0.25f * (1.f - pt) * (1.f - pt) * logpt;
        atomicAdd(&s_in[t], pt);
        atomicAdd(&s_ct[t], 1u);

#pragma unroll
        for (int c = 0; c < NC; c++) sp[c] += e[c] * inv;
    }

#pragma unroll
    for (int c = 0; c < NC; c++) {
        float v = sp[c];
#pragma unroll
        for (int d = 16; d; d >>= 1) v += __shfl_down_sync(0xffffffffu, v, d);
        if (l == 0) atomicAdd(&s_sp[c], v);
    }
#pragma unroll
    for (int d = 16; d; d >>= 1) {
        ce += __shfl_down_sync(0xffffffffu, ce, d);
        fo += __shfl_down_sync(0xffffffffu, fo, d);
    }
    if (l == 0) { atomicAdd(&s_ce, ce); atomicAdd(&s_fo, fo); }
    __syncthreads();

    if (tid < NC) {
        g_bsp[bid][tid] = s_sp[tid];
        g_bin[bid][tid] = s_in[tid];
        g_bct[bid][tid] = s_ct[tid];
    }
    if (tid == 32) g_bce[bid] = s_ce;
    if (tid == 33) g_bfo[bid] = s_fo;

    {
        uint4* dst4 = reinterpret_cast<uint4*>(g_part + (size_t)bid * HWORDS);
        const uint4* sh4 = reinterpret_cast<const uint4*>(sh);
        for (int i = tid; i < HWORDS / 4; i += NTHR) dst4[i] = sh4[i];
    }
    __syncthreads();   // all reads of sh done before phase B reuses it

    // ===================== BARRIER: dumps visible chip-wide =================
    if (tid == 0) {
        __threadfence();
        atomicAdd(&g_c1, 1u);
    }

    // ============================ PHASE B ==================================
    const int c = bid;
    if (c <= NC) {
        if (tid == 0) {
            while (atomicAdd(&g_c1, 0u) < (unsigned)NBLK) __nanosleep(64);
        }
        __syncthreads();
        __threadfence();   // acquire: partials + per-block scalars visible

        if (c == NC) {
            // scalar block: warp 0 = ce, warp 1 = fo, warps 2..20 = dice
            if (w == 0) {
                float v = 0.f;
                for (int r = l; r < NBLK; r += 32) v += g_bce[r];
#pragma unroll
                for (int d = 16; d; d >>= 1) v += __shfl_down_sync(0xffffffffu, v, d);
                if (l == 0) g_cefo[0] = v;
            } else if (w == 1) {
                float v = 0.f;
                for (int r = l; r < NBLK; r += 32) v += g_bfo[r];
#pragma unroll
                for (int d = 16; d; d >>= 1) v += __shfl_down_sync(0xffffffffu, v, d);
                if (l == 0) g_cefo[1] = v;
            } else if (w - 2 < NC) {
                const int cc = w - 2;
                float spv = 0.f, inv = 0.f;
                unsigned ct = 0u;
                for (int r = l; r < NBLK; r += 32) {
                    spv += g_bsp[r][cc];
                    inv += g_bin[r][cc];
                    ct  += g_bct[r][cc];
                }
#pragma unroll
                for (int d = 16; d; d >>= 1) {
                    spv += __shfl_down_sync(0xffffffffu, spv, d);
                    inv += __shfl_down_sync(0xffffffffu, inv, d);
                    ct  += __shfl_down_sync(0xffffffffu, ct, d);
                }
                if (l == 0) {
                    g_pres[cc] = ct;
                    const float u = spv + (float)ct;
                    g_dice[cc] = (ct > 0u)
                        ? __fdividef(2.f * inv + 1e-8f, u + 1e-8f) : 0.f;
                }
            }
        } else {
            // ---- merge class c's 148 partials: thread tid owns bucket tid --
            {
                unsigned acc = 0u;
                const unsigned off = (unsigned)c * NBUCK + tid;
#pragma unroll 4
                for (int r = 0; r < NBLK; r++)
                    acc += g_part[(size_t)r * HWORDS + off];
                sh[tid] = acc;
            }
            if (tid < 32) {   // per-class total count P
                unsigned p = 0u;
                for (int r = tid; r < NBLK; r += 32) p += g_bct[r][c];
#pragma unroll
                for (int d = 16; d; d >>= 1) p += __shfl_down_sync(0xffffffffu, p, d);
                if (tid == 0) sPv = p;
            }
            __syncthreads();

            const unsigned P = sPv;
            if (tid == 0) g_lov[c] = 0.f;
            double acc = 0.0;
            if (P > 0u) {
                const float Pf = (float)P;
                // single-chunk descending scan: 1024 buckets, 1024 threads
                const int idx = (NBUCK - 1) - tid;
                const unsigned cnt = sh[idx];
                const unsigned f = cnt >> 16;
                const unsigned gq = cnt & 0xFFFFu;

                unsigned fi = f, gi = gq;
#pragma unroll
                for (int d = 1; d < 32; d <<= 1) {
                    unsigned a = __shfl_up_sync(0xffffffffu, fi, d);
                    unsigned bb = __shfl_up_sync(0xffffffffu, gi, d);
                    if (l >= d) { fi += a; gi += bb; }
                }
                if (l == 31) { wF[w] = fi; wB[w] = gi; }
                __syncthreads();

                unsigned aF = 0u, aB = 0u;
                for (int k = 0; k < w; k++) { aF += wF[k]; aB += wB[k]; }

                if (cnt) {
                    const float Fi = (float)(aF + fi);
                    const float Bi = (float)(aB + gi);
                    const float Fe = Fi - (float)f;
                    const float Be = Bi - (float)gq;
                    const float e_rep = ((float)idx + 0.5f) * (1.0f / 128.0f);
                    const float num = (Pf - Fe) * (float)gq + (float)f * (Pf + Be);
                    const float den = (Pf + Be) * (Pf + Bi);
                    acc = (double)(e_rep * __fdividef(num, den));
                }
                __syncthreads();

#pragma unroll
                for (int d = 16; d; d >>= 1) acc += __shfl_down_sync(0xffffffffu, acc, d);
                if (l == 0) red[w] = acc;
                __syncthreads();
                if (tid < 32) {
                    double v = red[tid];
#pragma unroll
                    for (int d = 16; d; d >>= 1) v += __shfl_down_sync(0xffffffffu, v, d);
                    if (tid == 0) g_lov[c] = (float)v;
                }
            }
        }
    }

    // ==================== COMPLETION: last block combines ==================
    __threadfence();
    __syncthreads();
    if (tid == 0) s_last = (atomicAdd(&g_c3, 1u) == (unsigned)(NBLK - 1));
    __syncthreads();
    if (s_last) {
        __threadfence();   // acquire all scan/scalar results
        if (tid < 32) {
            float lov = 0.f, ds = 0.f, np = 0.f;
            if (tid < NC) {
                lov = g_lov[tid];
                if (g_pres[tid] > 0u) { ds = g_dice[tid]; np = 1.f; }
            }
#pragma unroll
            for (int d = 16; d; d >>= 1) {
                lov += __shfl_down_sync(0xffffffffu, lov, d);
                ds  += __shfl_down_sync(0xffffffffu, ds, d);
                np  += __shfl_down_sync(0xffffffffu, np, d);
            }
            if (tid == 0) {
                const double Nd = (double)NPIX;
                const double dice = (np > 0.f) ? (1.0 - (double)ds / (double)np) : 1.0;
                out[0] = (float)((double)g_cefo[0] / Nd + dice +
                                 (double)g_cefo[1] / Nd +
                                 0.5 * (double)lov / (double)NC);
                g_c1 = 0u;     // reset for next replay; safe: all 148 arrived
                g_c3 = 0u;
                __threadfence();
            }
        }
    }
}

// ---------------------------------------------------------------------------
extern "C" void kernel_launch(void* const* d_in, const int* in_sizes, int n_in,
                              void* d_out, int out_size)
{
    const float* logits;
    const int* masks;
    if (in_sizes[0] == LOGITS_ELEMS) {
        logits = (const float*)d_in[0];
        masks  = (const int*)d_in[1];
    } else {
        logits = (const float*)d_in[1];
        masks  = (const int*)d_in[0];
    }
    float* out = (float*)d_out;

    cudaFuncSetAttribute(fused_kernel,
                         cudaFuncAttributeMaxDynamicSharedMemorySize, SMEM_BYTES);

    fused_kernel<<<NBLK, NTHR, SMEM_BYTES>>>(logits, masks, out);
}